// round 2
// baseline (speedup 1.0000x reference)
#include <cuda_runtime.h>
#include <cuda_bf16.h>
#include <math.h>

// ---------------------------------------------------------------------------
// WindowAttention (Swin): B_=2048 windows, N=49 tokens, C=256, H=8, Dh=32
//   1) qkv = x @ qkv_w^T + qkv_b          (100352 x 256) @ (256 x 768)
//   2) per-(window,head) attention with relative-position bias + window mask
//   3) out  = attn_out @ proj_w^T + proj_b (100352 x 256) @ (256 x 256)
// fp32 throughout (1e-3 rel-err gate; tensor-core variants need a measured
// error budget first). Double-buffered SGEMM this round.
// ---------------------------------------------------------------------------

#define B_WIN   2048
#define NTOK    49
#define DIM     256
#define NHEAD   8
#define DHEAD   32
#define NWIN    64          // mask leading dim; window id = b % 64
#define MROWS   (B_WIN * NTOK)        // 100352
#define QKV_N   (3 * DIM)             // 768

// Scratch (static device globals: allocation-guard safe)
__device__ float g_qkv[(size_t)MROWS * QKV_N];    // ~308 MB
__device__ float g_attnout[(size_t)MROWS * DIM];  // ~103 MB

// ---------------------------------------------------------------------------
// SGEMM: C[M,N] = A[M,K] @ B[N,K]^T + bias[N]
// BM=BN=128, BK=16, 256 threads, 8x8 per-thread microtile,
// double-buffered shared-memory pipeline (1 barrier / K-step).
// Assumes M%128==0, N%128==0, K%16==0 (true for both calls).
// ---------------------------------------------------------------------------
#define BM 128
#define BN 128
#define BK 16
#define TM 8
#define TN 8

__global__ __launch_bounds__(256) void sgemm_nt_bias(
    const float* __restrict__ A, const float* __restrict__ Bm,
    const float* __restrict__ bias, float* __restrict__ C,
    int M, int N, int K)
{
    __shared__ float As[2][BK][BM];
    __shared__ float Bs[2][BK][BN];

    const int tid = threadIdx.x;
    const int tx = tid & 15;          // 0..15  -> N direction
    const int ty = tid >> 4;          // 0..15  -> M direction
    const int m0 = blockIdx.y * BM;
    const int n0 = blockIdx.x * BN;

    // Per-thread staging coords: 2 float4 from A, 2 from B per tile.
    const int r0 = tid >> 2;                 // rows 0..63   (l=0)
    const int r1 = r0 + 64;                  // rows 64..127 (l=1)
    const int c4 = (tid & 3) * 4;            // k-offset 0,4,8,12

    const float* Ap0 = A + (size_t)(m0 + r0) * K + c4;
    const float* Ap1 = A + (size_t)(m0 + r1) * K + c4;
    const float* Bp0 = Bm + (size_t)(n0 + r0) * K + c4;
    const float* Bp1 = Bm + (size_t)(n0 + r1) * K + c4;

    float acc[TM][TN];
#pragma unroll
    for (int i = 0; i < TM; i++)
#pragma unroll
        for (int j = 0; j < TN; j++) acc[i][j] = 0.f;

    float4 pa0, pa1, pb0, pb1;

    // Preload tile 0 into buffer 0
    pa0 = *reinterpret_cast<const float4*>(Ap0);
    pa1 = *reinterpret_cast<const float4*>(Ap1);
    pb0 = *reinterpret_cast<const float4*>(Bp0);
    pb1 = *reinterpret_cast<const float4*>(Bp1);
    {
        As[0][c4 + 0][r0] = pa0.x; As[0][c4 + 1][r0] = pa0.y;
        As[0][c4 + 2][r0] = pa0.z; As[0][c4 + 3][r0] = pa0.w;
        As[0][c4 + 0][r1] = pa1.x; As[0][c4 + 1][r1] = pa1.y;
        As[0][c4 + 2][r1] = pa1.z; As[0][c4 + 3][r1] = pa1.w;
        Bs[0][c4 + 0][r0] = pb0.x; Bs[0][c4 + 1][r0] = pb0.y;
        Bs[0][c4 + 2][r0] = pb0.z; Bs[0][c4 + 3][r0] = pb0.w;
        Bs[0][c4 + 0][r1] = pb1.x; Bs[0][c4 + 1][r1] = pb1.y;
        Bs[0][c4 + 2][r1] = pb1.z; Bs[0][c4 + 3][r1] = pb1.w;
    }
    __syncthreads();

    int buf = 0;
    for (int k0 = 0; k0 < K; k0 += BK) {
        const bool has_next = (k0 + BK) < K;
        // Prefetch next tile into registers (overlaps with FFMA below)
        if (has_next) {
            pa0 = *reinterpret_cast<const float4*>(Ap0 + k0 + BK);
            pa1 = *reinterpret_cast<const float4*>(Ap1 + k0 + BK);
            pb0 = *reinterpret_cast<const float4*>(Bp0 + k0 + BK);
            pb1 = *reinterpret_cast<const float4*>(Bp1 + k0 + BK);
        }

        // Compute from current buffer
#pragma unroll
        for (int kk = 0; kk < BK; kk++) {
            float ar[TM], br[TN];
#pragma unroll
            for (int i = 0; i < TM; i++) ar[i] = As[buf][kk][ty * TM + i];
#pragma unroll
            for (int j = 0; j < TN; j++) br[j] = Bs[buf][kk][tx * TN + j];
#pragma unroll
            for (int i = 0; i < TM; i++)
#pragma unroll
                for (int j = 0; j < TN; j++)
                    acc[i][j] = fmaf(ar[i], br[j], acc[i][j]);
        }

        // Store prefetched tile into the other buffer, then one barrier
        if (has_next) {
            const int nb = buf ^ 1;
            As[nb][c4 + 0][r0] = pa0.x; As[nb][c4 + 1][r0] = pa0.y;
            As[nb][c4 + 2][r0] = pa0.z; As[nb][c4 + 3][r0] = pa0.w;
            As[nb][c4 + 0][r1] = pa1.x; As[nb][c4 + 1][r1] = pa1.y;
            As[nb][c4 + 2][r1] = pa1.z; As[nb][c4 + 3][r1] = pa1.w;
            Bs[nb][c4 + 0][r0] = pb0.x; Bs[nb][c4 + 1][r0] = pb0.y;
            Bs[nb][c4 + 2][r0] = pb0.z; Bs[nb][c4 + 3][r0] = pb0.w;
            Bs[nb][c4 + 0][r1] = pb1.x; Bs[nb][c4 + 1][r1] = pb1.y;
            Bs[nb][c4 + 2][r1] = pb1.z; Bs[nb][c4 + 3][r1] = pb1.w;
            __syncthreads();
            buf = nb;
        }
    }

    // Epilogue: += bias, vectorized stores
#pragma unroll
    for (int i = 0; i < TM; i++) {
        int m = m0 + ty * TM + i;
#pragma unroll
        for (int j = 0; j < TN; j += 4) {
            int n = n0 + tx * TN + j;
            float4 v;
            v.x = acc[i][j + 0] + bias[n + 0];
            v.y = acc[i][j + 1] + bias[n + 1];
            v.z = acc[i][j + 2] + bias[n + 2];
            v.w = acc[i][j + 3] + bias[n + 3];
            *reinterpret_cast<float4*>(&C[(size_t)m * N + n]) = v;
        }
    }
}

// ---------------------------------------------------------------------------
// Windowed attention: one block per (window b, head h). 256 threads.
// qkv layout: [m=b*49+t][768], q at col h*32+d, k at +256, v at +512.
// Output written in [b][t][h*32+d] layout (ready for proj GEMM).
// ---------------------------------------------------------------------------
__global__ __launch_bounds__(256) void win_attn(
    const float* __restrict__ qkv, const float* __restrict__ mask,
    const float* __restrict__ rpb_table, const int* __restrict__ rel_index,
    float* __restrict__ out)
{
    const int b = blockIdx.x;
    const int h = blockIdx.y;
    const int tid = threadIdx.x;

    __shared__ float qs[NTOK][DHEAD];       // scaled q
    __shared__ float ks[NTOK][DHEAD + 1];   // +1 pad: kill 32-way conflict on k^T
    __shared__ float vs[NTOK][DHEAD];
    __shared__ float lg[NTOK][52];          // logits / probs, padded

    const float scale = 0.1767766952966369f;  // 32^-0.5

    const size_t base = (size_t)b * NTOK * QKV_N + (size_t)h * DHEAD;
    for (int idx = tid; idx < NTOK * DHEAD; idx += 256) {
        int t = idx >> 5, d = idx & 31;
        size_t off = base + (size_t)t * QKV_N + d;
        qs[t][d] = qkv[off] * scale;
        ks[t][d] = qkv[off + DIM];
        vs[t][d] = qkv[off + 2 * DIM];
    }
    __syncthreads();

    const float* mk = mask + (size_t)(b & (NWIN - 1)) * (NTOK * NTOK);
    for (int idx = tid; idx < NTOK * NTOK; idx += 256) {
        int i = idx / NTOK, j = idx - i * NTOK;
        float s = 0.f;
#pragma unroll
        for (int d = 0; d < DHEAD; d++) s = fmaf(qs[i][d], ks[j][d], s);
        s += rpb_table[rel_index[idx] * NHEAD + h] + mk[idx];
        lg[i][j] = s;
    }
    __syncthreads();

    if (tid < NTOK) {
        float mx = -1e30f;
#pragma unroll
        for (int j = 0; j < NTOK; j++) mx = fmaxf(mx, lg[tid][j]);
        float sum = 0.f;
#pragma unroll
        for (int j = 0; j < NTOK; j++) {
            float e = expf(lg[tid][j] - mx);
            lg[tid][j] = e;
            sum += e;
        }
        float inv = 1.f / sum;
#pragma unroll
        for (int j = 0; j < NTOK; j++) lg[tid][j] *= inv;
    }
    __syncthreads();

    float* outp = out + (size_t)b * NTOK * DIM + (size_t)h * DHEAD;
    for (int idx = tid; idx < NTOK * DHEAD; idx += 256) {
        int t = idx >> 5, d = idx & 31;
        float s = 0.f;
#pragma unroll
        for (int j = 0; j < NTOK; j++) s = fmaf(lg[t][j], vs[j][d], s);
        outp[(size_t)t * DIM + d] = s;
    }
}

// ---------------------------------------------------------------------------
// Launch
// Inputs (metadata order): 0:x 1:mask 2:qkv_w 3:qkv_b 4:proj_w 5:proj_b
//                          6:rpb_table 7:rel_index
// ---------------------------------------------------------------------------
extern "C" void kernel_launch(void* const* d_in, const int* in_sizes, int n_in,
                              void* d_out, int out_size)
{
    const float* x         = (const float*)d_in[0];
    const float* mask      = (const float*)d_in[1];
    const float* qkv_w     = (const float*)d_in[2];
    const float* qkv_b     = (const float*)d_in[3];
    const float* proj_w    = (const float*)d_in[4];
    const float* proj_b    = (const float*)d_in[5];
    const float* rpb_table = (const float*)d_in[6];
    const int*   rel_index = (const int*)d_in[7];
    float* out = (float*)d_out;

    float* qkv;
    float* attn;
    cudaGetSymbolAddress((void**)&qkv,  g_qkv);
    cudaGetSymbolAddress((void**)&attn, g_attnout);

    // 1) QKV GEMM: (100352 x 256) @ (768 x 256)^T -> (100352 x 768)
    {
        dim3 grid(QKV_N / BN, MROWS / BM);   // (6, 784)
        sgemm_nt_bias<<<grid, 256>>>(x, qkv_w, qkv_b, qkv, MROWS, QKV_N, DIM);
    }

    // 2) Windowed attention
    {
        dim3 grid(B_WIN, NHEAD);             // (2048, 8)
        win_attn<<<grid, 256>>>(qkv, mask, rpb_table, rel_index, attn);
    }

    // 3) Proj GEMM: (100352 x 256) @ (256 x 256)^T -> (100352 x 256)
    {
        dim3 grid(DIM / BN, MROWS / BM);     // (2, 784)
        sgemm_nt_bias<<<grid, 256>>>(attn, proj_w, proj_b, out, MROWS, DIM, DIM);
    }
}

// round 3
// speedup vs baseline: 1.2771x; 1.2771x over previous
#include <cuda_runtime.h>
#include <cuda_bf16.h>
#include <mma.h>
#include <math.h>

using namespace nvcuda;

// ---------------------------------------------------------------------------
// WindowAttention (Swin): B_=2048 windows, N=49 tokens, C=256, H=8, Dh=32
//   1) qkv = x @ qkv_w^T + qkv_b           -- tf32 tensor-core GEMM
//   2) per-(window,head) attention (fp32, smem-microtiled)
//   3) out  = attn_out @ proj_w^T + proj_b -- tf32 tensor-core GEMM
// ---------------------------------------------------------------------------

#define B_WIN   2048
#define NTOK    49
#define DIM     256
#define NHEAD   8
#define DHEAD   32
#define NWIN    64
#define MROWS   (B_WIN * NTOK)        // 100352
#define QKV_N   (3 * DIM)             // 768

__device__ float g_qkv[(size_t)MROWS * QKV_N];    // ~308 MB
__device__ float g_attnout[(size_t)MROWS * DIM];  // ~103 MB

__device__ __forceinline__ float f2tf32(float x) {
    unsigned u;
    asm("cvt.rna.tf32.f32 %0, %1;" : "=r"(u) : "f"(x));
    return __uint_as_float(u);
}

// ---------------------------------------------------------------------------
// tf32 GEMM: C[M,N] = A[M,K] @ B[N,K]^T + bias[N]
// BM=BN=128, BK=16, 256 threads (8 warps: 4 in M x 2 in N),
// per-warp tile 32x64 via 2x4 wmma m16n16k8 fragments.
// Double-buffered smem with register prefetch.
// Requires M%128==0, N%128==0, K%16==0.
// ---------------------------------------------------------------------------
#define BM 128
#define BN 128
#define BK 16

__global__ __launch_bounds__(256) void gemm_tf32_nt_bias(
    const float* __restrict__ A, const float* __restrict__ Bm,
    const float* __restrict__ bias, float* __restrict__ C,
    int M, int N, int K)
{
    // [row][k] layout, ld = 16 floats (64B rows -> conflict-free f4 STS)
    __shared__ float As[2][BM][BK];
    __shared__ float Bs[2][BN][BK];
    __shared__ float biasTile[16][BN];

    const int tid = threadIdx.x;
    const int wid = tid >> 5;
    const int wm  = wid & 3;          // warp row   (4 x 32 rows)
    const int wn  = wid >> 2;         // warp col   (2 x 64 cols)
    const int m0 = blockIdx.y * BM;
    const int n0 = blockIdx.x * BN;

    // Staging coords: 2 float4 per matrix per thread.
    const int r0 = tid >> 2;          // 0..63
    const int r1 = r0 + 64;           // 64..127
    const int c4 = (tid & 3) * 4;     // 0,4,8,12

    const float* Ap0 = A + (size_t)(m0 + r0) * K + c4;
    const float* Ap1 = A + (size_t)(m0 + r1) * K + c4;
    const float* Bp0 = Bm + (size_t)(n0 + r0) * K + c4;
    const float* Bp1 = Bm + (size_t)(n0 + r1) * K + c4;

    // Bias replicated into a 16-row tile so acc fragments start at bias.
    for (int i = tid; i < 16 * BN; i += 256)
        biasTile[i >> 7][i & 127] = bias[n0 + (i & 127)];

    wmma::fragment<wmma::accumulator, 16, 16, 8, float> acc[2][4];

    float4 pa0, pa1, pb0, pb1;

    // Preload tile 0 (tf32-converted at STS)
    pa0 = *reinterpret_cast<const float4*>(Ap0);
    pa1 = *reinterpret_cast<const float4*>(Ap1);
    pb0 = *reinterpret_cast<const float4*>(Bp0);
    pb1 = *reinterpret_cast<const float4*>(Bp1);
    {
        float4 t;
        t.x=f2tf32(pa0.x); t.y=f2tf32(pa0.y); t.z=f2tf32(pa0.z); t.w=f2tf32(pa0.w);
        *reinterpret_cast<float4*>(&As[0][r0][c4]) = t;
        t.x=f2tf32(pa1.x); t.y=f2tf32(pa1.y); t.z=f2tf32(pa1.z); t.w=f2tf32(pa1.w);
        *reinterpret_cast<float4*>(&As[0][r1][c4]) = t;
        t.x=f2tf32(pb0.x); t.y=f2tf32(pb0.y); t.z=f2tf32(pb0.z); t.w=f2tf32(pb0.w);
        *reinterpret_cast<float4*>(&Bs[0][r0][c4]) = t;
        t.x=f2tf32(pb1.x); t.y=f2tf32(pb1.y); t.z=f2tf32(pb1.z); t.w=f2tf32(pb1.w);
        *reinterpret_cast<float4*>(&Bs[0][r1][c4]) = t;
    }
    __syncthreads();

    // Init accumulators from bias tile
#pragma unroll
    for (int mi = 0; mi < 2; mi++)
#pragma unroll
        for (int ni = 0; ni < 4; ni++)
            wmma::load_matrix_sync(acc[mi][ni], &biasTile[0][wn * 64 + ni * 16],
                                   BN, wmma::mem_row_major);

    int buf = 0;
    for (int k0 = 0; k0 < K; k0 += BK) {
        const bool has_next = (k0 + BK) < K;
        if (has_next) {
            pa0 = *reinterpret_cast<const float4*>(Ap0 + k0 + BK);
            pa1 = *reinterpret_cast<const float4*>(Ap1 + k0 + BK);
            pb0 = *reinterpret_cast<const float4*>(Bp0 + k0 + BK);
            pb1 = *reinterpret_cast<const float4*>(Bp1 + k0 + BK);
        }

#pragma unroll
        for (int ks = 0; ks < BK; ks += 8) {
            wmma::fragment<wmma::matrix_a, 16, 16, 8, wmma::precision::tf32,
                           wmma::row_major> fa[2];
            wmma::fragment<wmma::matrix_b, 16, 16, 8, wmma::precision::tf32,
                           wmma::col_major> fb[4];
#pragma unroll
            for (int mi = 0; mi < 2; mi++)
                wmma::load_matrix_sync(fa[mi], &As[buf][wm * 32 + mi * 16][ks], BK);
#pragma unroll
            for (int ni = 0; ni < 4; ni++)
                wmma::load_matrix_sync(fb[ni], &Bs[buf][wn * 64 + ni * 16][ks], BK);
#pragma unroll
            for (int mi = 0; mi < 2; mi++)
#pragma unroll
                for (int ni = 0; ni < 4; ni++)
                    wmma::mma_sync(acc[mi][ni], fa[mi], fb[ni], acc[mi][ni]);
        }

        if (has_next) {
            const int nb = buf ^ 1;
            float4 t;
            t.x=f2tf32(pa0.x); t.y=f2tf32(pa0.y); t.z=f2tf32(pa0.z); t.w=f2tf32(pa0.w);
            *reinterpret_cast<float4*>(&As[nb][r0][c4]) = t;
            t.x=f2tf32(pa1.x); t.y=f2tf32(pa1.y); t.z=f2tf32(pa1.z); t.w=f2tf32(pa1.w);
            *reinterpret_cast<float4*>(&As[nb][r1][c4]) = t;
            t.x=f2tf32(pb0.x); t.y=f2tf32(pb0.y); t.z=f2tf32(pb0.z); t.w=f2tf32(pb0.w);
            *reinterpret_cast<float4*>(&Bs[nb][r0][c4]) = t;
            t.x=f2tf32(pb1.x); t.y=f2tf32(pb1.y); t.z=f2tf32(pb1.z); t.w=f2tf32(pb1.w);
            *reinterpret_cast<float4*>(&Bs[nb][r1][c4]) = t;
            __syncthreads();
            buf = nb;
        }
    }

    // Epilogue: bias already inside acc; store straight to C.
#pragma unroll
    for (int mi = 0; mi < 2; mi++)
#pragma unroll
        for (int ni = 0; ni < 4; ni++)
            wmma::store_matrix_sync(
                &C[(size_t)(m0 + wm * 32 + mi * 16) * N + n0 + wn * 64 + ni * 16],
                acc[mi][ni], N, wmma::mem_row_major);
}

// ---------------------------------------------------------------------------
// Windowed attention: one block per (window b, head h). 256 threads.
// i-pair microtile in QK (halves k smem bytes), t-pair in PV (halves v bytes),
// warp-per-row softmax with shfl reductions.
// ---------------------------------------------------------------------------
#define QPAD 36   // 144B rows: 16B-aligned, stride-4 bank rotation

__global__ __launch_bounds__(256) void win_attn(
    const float* __restrict__ qkv, const float* __restrict__ mask,
    const float* __restrict__ rpb_table, const int* __restrict__ rel_index,
    float* __restrict__ out)
{
    const int b = blockIdx.x;
    const int h = blockIdx.y;
    const int tid = threadIdx.x;
    const int wid = tid >> 5;
    const int lane = tid & 31;

    __shared__ float qs[50][QPAD];   // row 49 = scratch (i-pair overrun)
    __shared__ float ks[49][QPAD];
    __shared__ float vs[49][QPAD];
    __shared__ float lg[50][52];     // row 49 = scratch

    const float scale = 0.1767766952966369f;  // 32^-0.5

    const size_t base = (size_t)b * NTOK * QKV_N + (size_t)h * DHEAD;
    for (int idx = tid; idx < NTOK * DHEAD; idx += 256) {
        int t = idx >> 5, d = idx & 31;
        size_t off = base + (size_t)t * QKV_N + d;
        qs[t][d] = qkv[off] * scale;
        ks[t][d] = qkv[off + DIM];
        vs[t][d] = qkv[off + 2 * DIM];
    }
    __syncthreads();

    // Logits: thread handles (i0,j) and (i1=i0+25,j); k4 loaded once per pair.
    const float* mk = mask + (size_t)(b & (NWIN - 1)) * (NTOK * NTOK);
    for (int idx = tid; idx < 25 * NTOK; idx += 256) {
        int i0 = idx / NTOK, j = idx - i0 * NTOK;
        int i1 = i0 + 25;
        const float4* q40 = reinterpret_cast<const float4*>(qs[i0]);
        const float4* q41 = reinterpret_cast<const float4*>(qs[i1]);
        const float4* k4  = reinterpret_cast<const float4*>(ks[j]);
        float s0 = 0.f, s1 = 0.f;
#pragma unroll
        for (int dd = 0; dd < 8; dd++) {
            float4 kv = k4[dd];
            float4 q0 = q40[dd];
            float4 q1 = q41[dd];
            s0 = fmaf(q0.x, kv.x, s0); s0 = fmaf(q0.y, kv.y, s0);
            s0 = fmaf(q0.z, kv.z, s0); s0 = fmaf(q0.w, kv.w, s0);
            s1 = fmaf(q1.x, kv.x, s1); s1 = fmaf(q1.y, kv.y, s1);
            s1 = fmaf(q1.z, kv.z, s1); s1 = fmaf(q1.w, kv.w, s1);
        }
        lg[i0][j] = s0 + rpb_table[rel_index[i0 * NTOK + j] * NHEAD + h]
                       + mk[i0 * NTOK + j];
        if (i1 < NTOK)
            lg[i1][j] = s1 + rpb_table[rel_index[i1 * NTOK + j] * NHEAD + h]
                           + mk[i1 * NTOK + j];
    }
    __syncthreads();

    // Softmax: warp per row; lane covers j=lane and j=lane+32.
    for (int r = wid; r < NTOK; r += 8) {
        int j1 = lane + 32;
        float v0 = (lane < NTOK) ? lg[r][lane] : -1e30f;
        float v1 = (j1 < NTOK) ? lg[r][j1] : -1e30f;
        float mx = fmaxf(v0, v1);
#pragma unroll
        for (int o = 16; o > 0; o >>= 1)
            mx = fmaxf(mx, __shfl_xor_sync(0xffffffffu, mx, o));
        float e0 = (lane < NTOK) ? __expf(v0 - mx) : 0.f;
        float e1 = (j1 < NTOK) ? __expf(v1 - mx) : 0.f;
        float sum = e0 + e1;
#pragma unroll
        for (int o = 16; o > 0; o >>= 1)
            sum += __shfl_xor_sync(0xffffffffu, sum, o);
        float inv = 1.f / sum;
        if (lane < NTOK) lg[r][lane] = e0 * inv;
        if (j1 < NTOK) lg[r][j1] = e1 * inv;
    }
    __syncthreads();

    // P @ V: thread handles (t0,d) and (t1=t0+25,d); v loaded once per pair.
    float* outp = out + (size_t)b * NTOK * DIM + (size_t)h * DHEAD;
    for (int idx = tid; idx < 25 * DHEAD; idx += 256) {
        int t0 = idx >> 5, d = idx & 31;
        int t1 = t0 + 25;
        float s0 = 0.f, s1 = 0.f;
#pragma unroll
        for (int j = 0; j < NTOK; j++) {
            float vv = vs[j][d];
            s0 = fmaf(lg[t0][j], vv, s0);
            s1 = fmaf(lg[t1][j], vv, s1);
        }
        outp[(size_t)t0 * DIM + d] = s0;
        if (t1 < NTOK) outp[(size_t)t1 * DIM + d] = s1;
    }
}

// ---------------------------------------------------------------------------
// Launch
// Inputs: 0:x 1:mask 2:qkv_w 3:qkv_b 4:proj_w 5:proj_b 6:rpb_table 7:rel_index
// ---------------------------------------------------------------------------
extern "C" void kernel_launch(void* const* d_in, const int* in_sizes, int n_in,
                              void* d_out, int out_size)
{
    const float* x         = (const float*)d_in[0];
    const float* mask      = (const float*)d_in[1];
    const float* qkv_w     = (const float*)d_in[2];
    const float* qkv_b     = (const float*)d_in[3];
    const float* proj_w    = (const float*)d_in[4];
    const float* proj_b    = (const float*)d_in[5];
    const float* rpb_table = (const float*)d_in[6];
    const int*   rel_index = (const int*)d_in[7];
    float* out = (float*)d_out;

    float* qkv;
    float* attn;
    cudaGetSymbolAddress((void**)&qkv,  g_qkv);
    cudaGetSymbolAddress((void**)&attn, g_attnout);

    // 1) QKV GEMM: (100352 x 256) @ (768 x 256)^T -> (100352 x 768)
    {
        dim3 grid(QKV_N / BN, MROWS / BM);   // (6, 784)
        gemm_tf32_nt_bias<<<grid, 256>>>(x, qkv_w, qkv_b, qkv, MROWS, QKV_N, DIM);
    }

    // 2) Windowed attention
    {
        dim3 grid(B_WIN, NHEAD);             // (2048, 8)
        win_attn<<<grid, 256>>>(qkv, mask, rpb_table, rel_index, attn);
    }

    // 3) Proj GEMM: (100352 x 256) @ (256 x 256)^T -> (100352 x 256)
    {
        dim3 grid(DIM / BN, MROWS / BM);     // (2, 784)
        gemm_tf32_nt_bias<<<grid, 256>>>(attn, proj_w, proj_b, out, MROWS, DIM, DIM);
    }
}

// round 9
// speedup vs baseline: 1.5560x; 1.2184x over previous
#include <cuda_runtime.h>
#include <cuda_bf16.h>
#include <mma.h>
#include <math.h>

using namespace nvcuda;

// ---------------------------------------------------------------------------
// WindowAttention (Swin): B_=2048 windows, N=49 tokens, C=256, H=8, Dh=32
//   1) qkv = x @ qkv_w^T + qkv_b           -- tf32 tensor-core GEMM
//   2) per-(window,head) attention (fp32, smem-microtiled, precomputed rpb)
//   3) out  = attn_out @ proj_w^T + proj_b -- tf32 tensor-core GEMM
// R9 = R8 resubmit (broker timeout): BKP=20 pad, rpb precompute,
//     float4 staging, __launch_bounds__(256,2) on the GEMM.
// ---------------------------------------------------------------------------

#define B_WIN   2048
#define NTOK    49
#define DIM     256
#define NHEAD   8
#define DHEAD   32
#define NWIN    64
#define MROWS   (B_WIN * NTOK)        // 100352
#define QKV_N   (3 * DIM)             // 768
#define NN      (NTOK * NTOK)         // 2401

__device__ float g_qkv[(size_t)MROWS * QKV_N];    // ~308 MB
__device__ float g_attnout[(size_t)MROWS * DIM];  // ~103 MB
__device__ float g_rpb[NHEAD * NN];               // gathered bias, 77 KB

__device__ __forceinline__ float f2tf32(float x) {
    unsigned u;
    asm("cvt.rna.tf32.f32 %0, %1;" : "=r"(u) : "f"(x));
    return __uint_as_float(u);
}

// ---------------------------------------------------------------------------
// rpb precompute: g_rpb[h][ij] = rpb_table[rel_index[ij]*H + h]
// ---------------------------------------------------------------------------
__global__ void gather_rpb(const float* __restrict__ rpb_table,
                           const int* __restrict__ rel_index,
                           float* __restrict__ rpb_g)
{
    int idx = blockIdx.x * blockDim.x + threadIdx.x;
    if (idx >= NHEAD * NN) return;
    int h = idx / NN, ij = idx - h * NN;
    rpb_g[idx] = rpb_table[rel_index[ij] * NHEAD + h];
}

// ---------------------------------------------------------------------------
// tf32 GEMM: C[M,N] = A[M,K] @ B[N,K]^T + bias[N]
// BM=BN=128, BK=16 (rows padded to ld=20), 256 threads (8 warps: 4M x 2N),
// per-warp tile 32x64 via 2x4 wmma m16n16k8 fragments, double-buffered.
// __launch_bounds__(256,2): cap regs at 128 so 2 CTAs co-reside per SM.
// Requires M%128==0, N%128==0, K%16==0.
// ---------------------------------------------------------------------------
#define BM 128
#define BN 128
#define BK 16
#define BKP 20   // padded row: 80B -> row starts rotate through 8 bank groups

__global__ __launch_bounds__(256, 2) void gemm_tf32_nt_bias(
    const float* __restrict__ A, const float* __restrict__ Bm,
    const float* __restrict__ bias, float* __restrict__ C,
    int M, int N, int K)
{
    __shared__ float As[2][BM][BKP];
    __shared__ float Bs[2][BN][BKP];
    __shared__ float biasTile[16][BN];

    const int tid = threadIdx.x;
    const int wid = tid >> 5;
    const int wm  = wid & 3;          // warp row   (4 x 32 rows)
    const int wn  = wid >> 2;         // warp col   (2 x 64 cols)
    const int m0 = blockIdx.y * BM;
    const int n0 = blockIdx.x * BN;

    // Staging coords: 2 float4 per matrix per thread.
    const int r0 = tid >> 2;          // 0..63
    const int r1 = r0 + 64;           // 64..127
    const int c4 = (tid & 3) * 4;     // 0,4,8,12

    const float* Ap0 = A + (size_t)(m0 + r0) * K + c4;
    const float* Ap1 = A + (size_t)(m0 + r1) * K + c4;
    const float* Bp0 = Bm + (size_t)(n0 + r0) * K + c4;
    const float* Bp1 = Bm + (size_t)(n0 + r1) * K + c4;

    for (int i = tid; i < 16 * BN; i += 256)
        biasTile[i >> 7][i & 127] = bias[n0 + (i & 127)];

    wmma::fragment<wmma::accumulator, 16, 16, 8, float> acc[2][4];

    float4 pa0, pa1, pb0, pb1;

    pa0 = *reinterpret_cast<const float4*>(Ap0);
    pa1 = *reinterpret_cast<const float4*>(Ap1);
    pb0 = *reinterpret_cast<const float4*>(Bp0);
    pb1 = *reinterpret_cast<const float4*>(Bp1);
    {
        float4 t;
        t.x=f2tf32(pa0.x); t.y=f2tf32(pa0.y); t.z=f2tf32(pa0.z); t.w=f2tf32(pa0.w);
        *reinterpret_cast<float4*>(&As[0][r0][c4]) = t;
        t.x=f2tf32(pa1.x); t.y=f2tf32(pa1.y); t.z=f2tf32(pa1.z); t.w=f2tf32(pa1.w);
        *reinterpret_cast<float4*>(&As[0][r1][c4]) = t;
        t.x=f2tf32(pb0.x); t.y=f2tf32(pb0.y); t.z=f2tf32(pb0.z); t.w=f2tf32(pb0.w);
        *reinterpret_cast<float4*>(&Bs[0][r0][c4]) = t;
        t.x=f2tf32(pb1.x); t.y=f2tf32(pb1.y); t.z=f2tf32(pb1.z); t.w=f2tf32(pb1.w);
        *reinterpret_cast<float4*>(&Bs[0][r1][c4]) = t;
    }
    __syncthreads();

#pragma unroll
    for (int mi = 0; mi < 2; mi++)
#pragma unroll
        for (int ni = 0; ni < 4; ni++)
            wmma::load_matrix_sync(acc[mi][ni], &biasTile[0][wn * 64 + ni * 16],
                                   BN, wmma::mem_row_major);

    int buf = 0;
    for (int k0 = 0; k0 < K; k0 += BK) {
        const bool has_next = (k0 + BK) < K;
        if (has_next) {
            pa0 = *reinterpret_cast<const float4*>(Ap0 + k0 + BK);
            pa1 = *reinterpret_cast<const float4*>(Ap1 + k0 + BK);
            pb0 = *reinterpret_cast<const float4*>(Bp0 + k0 + BK);
            pb1 = *reinterpret_cast<const float4*>(Bp1 + k0 + BK);
        }

#pragma unroll
        for (int ks = 0; ks < BK; ks += 8) {
            wmma::fragment<wmma::matrix_a, 16, 16, 8, wmma::precision::tf32,
                           wmma::row_major> fa[2];
            wmma::fragment<wmma::matrix_b, 16, 16, 8, wmma::precision::tf32,
                           wmma::col_major> fb[4];
#pragma unroll
            for (int mi = 0; mi < 2; mi++)
                wmma::load_matrix_sync(fa[mi], &As[buf][wm * 32 + mi * 16][ks], BKP);
#pragma unroll
            for (int ni = 0; ni < 4; ni++)
                wmma::load_matrix_sync(fb[ni], &Bs[buf][wn * 64 + ni * 16][ks], BKP);
#pragma unroll
            for (int mi = 0; mi < 2; mi++)
#pragma unroll
                for (int ni = 0; ni < 4; ni++)
                    wmma::mma_sync(acc[mi][ni], fa[mi], fb[ni], acc[mi][ni]);
        }

        if (has_next) {
            const int nb = buf ^ 1;
            float4 t;
            t.x=f2tf32(pa0.x); t.y=f2tf32(pa0.y); t.z=f2tf32(pa0.z); t.w=f2tf32(pa0.w);
            *reinterpret_cast<float4*>(&As[nb][r0][c4]) = t;
            t.x=f2tf32(pa1.x); t.y=f2tf32(pa1.y); t.z=f2tf32(pa1.z); t.w=f2tf32(pa1.w);
            *reinterpret_cast<float4*>(&As[nb][r1][c4]) = t;
            t.x=f2tf32(pb0.x); t.y=f2tf32(pb0.y); t.z=f2tf32(pb0.z); t.w=f2tf32(pb0.w);
            *reinterpret_cast<float4*>(&Bs[nb][r0][c4]) = t;
            t.x=f2tf32(pb1.x); t.y=f2tf32(pb1.y); t.z=f2tf32(pb1.z); t.w=f2tf32(pb1.w);
            *reinterpret_cast<float4*>(&Bs[nb][r1][c4]) = t;
            __syncthreads();
            buf = nb;
        }
    }

#pragma unroll
    for (int mi = 0; mi < 2; mi++)
#pragma unroll
        for (int ni = 0; ni < 4; ni++)
            wmma::store_matrix_sync(
                &C[(size_t)(m0 + wm * 32 + mi * 16) * N + n0 + wn * 64 + ni * 16],
                acc[mi][ni], N, wmma::mem_row_major);
}

// ---------------------------------------------------------------------------
// Windowed attention: one block per (window b, head h). 256 threads.
// float4 staging; i-pair QK microtile; warp-per-row softmax; t-pair PV.
// ---------------------------------------------------------------------------
#define QPAD 36

__global__ __launch_bounds__(256) void win_attn(
    const float* __restrict__ qkv, const float* __restrict__ mask,
    const float* __restrict__ rpb_g, float* __restrict__ out)
{
    const int b = blockIdx.x;
    const int h = blockIdx.y;
    const int tid = threadIdx.x;
    const int wid = tid >> 5;
    const int lane = tid & 31;

    __shared__ float qs[50][QPAD];   // row 49 = scratch (i-pair overrun)
    __shared__ float ks[49][QPAD];
    __shared__ float vs[49][QPAD];
    __shared__ float lg[50][52];     // row 49 = scratch

    const float scale = 0.1767766952966369f;  // 32^-0.5

    // Stage q/k/v as float4 (rows 16B aligned: base + t*768 + h*32 floats).
    const size_t base = (size_t)b * NTOK * QKV_N + (size_t)h * DHEAD;
    for (int idx = tid; idx < NTOK * (DHEAD / 4); idx += 256) {
        int t = idx >> 3, d4 = (idx & 7) * 4;
        size_t off = base + (size_t)t * QKV_N + d4;
        float4 q = *reinterpret_cast<const float4*>(&qkv[off]);
        float4 k = *reinterpret_cast<const float4*>(&qkv[off + DIM]);
        float4 v = *reinterpret_cast<const float4*>(&qkv[off + 2 * DIM]);
        q.x *= scale; q.y *= scale; q.z *= scale; q.w *= scale;
        *reinterpret_cast<float4*>(&qs[t][d4]) = q;
        *reinterpret_cast<float4*>(&ks[t][d4]) = k;
        *reinterpret_cast<float4*>(&vs[t][d4]) = v;
    }
    __syncthreads();

    const float* mk = mask + (size_t)(b & (NWIN - 1)) * NN;
    const float* bh = rpb_g + (size_t)h * NN;
    for (int idx = tid; idx < 25 * NTOK; idx += 256) {
        int i0 = idx / NTOK, j = idx - i0 * NTOK;
        int i1 = i0 + 25;
        const float4* q40 = reinterpret_cast<const float4*>(qs[i0]);
        const float4* q41 = reinterpret_cast<const float4*>(qs[i1]);
        const float4* k4  = reinterpret_cast<const float4*>(ks[j]);
        float s0 = 0.f, s1 = 0.f;
#pragma unroll
        for (int dd = 0; dd < 8; dd++) {
            float4 kv = k4[dd];
            float4 q0 = q40[dd];
            float4 q1 = q41[dd];
            s0 = fmaf(q0.x, kv.x, s0); s0 = fmaf(q0.y, kv.y, s0);
            s0 = fmaf(q0.z, kv.z, s0); s0 = fmaf(q0.w, kv.w, s0);
            s1 = fmaf(q1.x, kv.x, s1); s1 = fmaf(q1.y, kv.y, s1);
            s1 = fmaf(q1.z, kv.z, s1); s1 = fmaf(q1.w, kv.w, s1);
        }
        int e0i = i0 * NTOK + j;
        int e1i = i1 * NTOK + j;
        lg[i0][j] = s0 + bh[e0i] + mk[e0i];
        if (i1 < NTOK)
            lg[i1][j] = s1 + bh[e1i] + mk[e1i];
    }
    __syncthreads();

    // Softmax: warp per row; lane covers j=lane and j=lane+32.
    for (int r = wid; r < NTOK; r += 8) {
        int j1 = lane + 32;
        float v0 = (lane < NTOK) ? lg[r][lane] : -1e30f;
        float v1 = (j1 < NTOK) ? lg[r][j1] : -1e30f;
        float mx = fmaxf(v0, v1);
#pragma unroll
        for (int o = 16; o > 0; o >>= 1)
            mx = fmaxf(mx, __shfl_xor_sync(0xffffffffu, mx, o));
        float e0 = (lane < NTOK) ? __expf(v0 - mx) : 0.f;
        float e1 = (j1 < NTOK) ? __expf(v1 - mx) : 0.f;
        float sum = e0 + e1;
#pragma unroll
        for (int o = 16; o > 0; o >>= 1)
            sum += __shfl_xor_sync(0xffffffffu, sum, o);
        float inv = 1.f / sum;
        if (lane < NTOK) lg[r][lane] = e0 * inv;
        if (j1 < NTOK) lg[r][j1] = e1 * inv;
    }
    __syncthreads();

    // P @ V: thread handles (t0,d) and (t1=t0+25,d).
    float* outp = out + (size_t)b * NTOK * DIM + (size_t)h * DHEAD;
    for (int idx = tid; idx < 25 * DHEAD; idx += 256) {
        int t0 = idx >> 5, d = idx & 31;
        int t1 = t0 + 25;
        float s0 = 0.f, s1 = 0.f;
#pragma unroll
        for (int j = 0; j < NTOK; j++) {
            float vv = vs[j][d];
            s0 = fmaf(lg[t0][j], vv, s0);
            s1 = fmaf(lg[t1][j], vv, s1);
        }
        outp[(size_t)t0 * DIM + d] = s0;
        if (t1 < NTOK) outp[(size_t)t1 * DIM + d] = s1;
    }
}

// ---------------------------------------------------------------------------
// Launch
// Inputs: 0:x 1:mask 2:qkv_w 3:qkv_b 4:proj_w 5:proj_b 6:rpb_table 7:rel_index
// ---------------------------------------------------------------------------
extern "C" void kernel_launch(void* const* d_in, const int* in_sizes, int n_in,
                              void* d_out, int out_size)
{
    const float* x         = (const float*)d_in[0];
    const float* mask      = (const float*)d_in[1];
    const float* qkv_w     = (const float*)d_in[2];
    const float* qkv_b     = (const float*)d_in[3];
    const float* proj_w    = (const float*)d_in[4];
    const float* proj_b    = (const float*)d_in[5];
    const float* rpb_table = (const float*)d_in[6];
    const int*   rel_index = (const int*)d_in[7];
    float* out = (float*)d_out;

    float* qkv;
    float* attn;
    float* rpb_g;
    cudaGetSymbolAddress((void**)&qkv,   g_qkv);
    cudaGetSymbolAddress((void**)&attn,  g_attnout);
    cudaGetSymbolAddress((void**)&rpb_g, g_rpb);

    // 0) Gather rpb once (tiny)
    gather_rpb<<<(NHEAD * NN + 255) / 256, 256>>>(rpb_table, rel_index, rpb_g);

    // 1) QKV GEMM: (100352 x 256) @ (768 x 256)^T -> (100352 x 768)
    {
        dim3 grid(QKV_N / BN, MROWS / BM);   // (6, 784)
        gemm_tf32_nt_bias<<<grid, 256>>>(x, qkv_w, qkv_b, qkv, MROWS, QKV_N, DIM);
    }

    // 2) Windowed attention
    {
        dim3 grid(B_WIN, NHEAD);             // (2048, 8)
        win_attn<<<grid, 256>>>(qkv, mask, rpb_g, attn);
    }

    // 3) Proj GEMM: (100352 x 256) @ (256 x 256)^T -> (100352 x 256)
    {
        dim3 grid(DIM / BN, MROWS / BM);     // (2, 784)
        gemm_tf32_nt_bias<<<grid, 256>>>(attn, proj_w, proj_b, out, MROWS, DIM, DIM);
    }
}